// round 2
// baseline (speedup 1.0000x reference)
#include <cuda_runtime.h>

// ---------------------------------------------------------------------------
// TrajectoryDecoder: 2-layer LSTM (H=128), D=129, SEQ=12, OUT=2, B=131072.
// Fully fused: one CTA owns 32 batch rows for the whole 12-step recurrence.
// States live in SMEM (h) and registers (c). Weights pre-transposed k-major.
// ---------------------------------------------------------------------------

#define HH    128
#define DD    129
#define FOURH 512
#define SEQL  12
#define ROWS  32          // batch rows per CTA
#define LDT   36          // leading dim of k-major (transposed) h / x tiles
#define LDGS  520         // leading dim of 32x512 gate / pre0 tiles

// Pre-transposed weights (k-major: Wt[k*512 + c] = W[c*K + k]), +1 pad row
// for the prefetch overread in the GEMM inner loop.
__device__ float g_Wt_init[(DD + 1) * FOURH];
__device__ float g_Wt_ih0 [(DD + 1) * FOURH];
__device__ float g_Wt_hh0 [(HH + 1) * FOURH];
__device__ float g_Wt_ih1 [(HH + 1) * FOURH];
__device__ float g_Wt_hh1 [(HH + 1) * FOURH];
__device__ float g_bpre0[FOURH];   // b_ih_l0 + b_hh_l0
__device__ float g_bpre1[FOURH];   // b_ih_l1 + b_hh_l1

__global__ void prep_kernel(const float* __restrict__ W_init,
                            const float* __restrict__ W_ih0,
                            const float* __restrict__ W_hh0,
                            const float* __restrict__ b_ih0,
                            const float* __restrict__ b_hh0,
                            const float* __restrict__ W_ih1,
                            const float* __restrict__ W_hh1,
                            const float* __restrict__ b_ih1,
                            const float* __restrict__ b_hh1) {
    int c = blockIdx.x;            // 0..511 output unit
    int k = threadIdx.x;           // 0..159
    if (k < DD) {
        g_Wt_init[k * FOURH + c] = W_init[c * DD + k];
        g_Wt_ih0 [k * FOURH + c] = W_ih0 [c * DD + k];
    }
    if (k < HH) {
        g_Wt_hh0[k * FOURH + c] = W_hh0[c * HH + k];
        g_Wt_ih1[k * FOURH + c] = W_ih1[c * HH + k];
        g_Wt_hh1[k * FOURH + c] = W_hh1[c * HH + k];
    }
    if (k == 0) {
        g_bpre0[c] = b_ih0[c] + b_hh0[c];
        g_bpre1[c] = b_ih1[c] + b_hh1[c];
    }
}

__device__ __forceinline__ float sigmoidf_(float x) {
    return 1.0f / (1.0f + expf(-x));
}

// acc[8][8] += aT[0:K][r0..r0+7] (k-major shared, ld=LDT) * Wt[0:K][c0..c0+7]
template <int K>
__device__ __forceinline__ void gemm_acc(float (&acc)[8][8],
                                         const float* __restrict__ Wt,
                                         const float* aT, int r0, int c0) {
    float4 w0 = *(const float4*)(Wt + c0);
    float4 w1 = *(const float4*)(Wt + c0 + 4);
#pragma unroll 2
    for (int k = 0; k < K; ++k) {
        const float* wn = Wt + (k + 1) * FOURH + c0;   // prefetch (pad row ok)
        float4 nw0 = *(const float4*)(wn);
        float4 nw1 = *(const float4*)(wn + 4);
        float4 a0 = *(const float4*)(aT + k * LDT + r0);
        float4 a1 = *(const float4*)(aT + k * LDT + r0 + 4);
        float av[8] = {a0.x, a0.y, a0.z, a0.w, a1.x, a1.y, a1.z, a1.w};
        float wv[8] = {w0.x, w0.y, w0.z, w0.w, w1.x, w1.y, w1.z, w1.w};
#pragma unroll
        for (int i = 0; i < 8; ++i)
#pragma unroll
            for (int j = 0; j < 8; ++j)
                acc[i][j] = fmaf(av[i], wv[j], acc[i][j]);
        w0 = nw0; w1 = nw1;
    }
}

__device__ __forceinline__ void store_acc(float* dst, float (&acc)[8][8],
                                          int r0, int c0) {
#pragma unroll
    for (int i = 0; i < 8; ++i) {
        float4* p = (float4*)(dst + (r0 + i) * LDGS + c0);
        p[0] = make_float4(acc[i][0], acc[i][1], acc[i][2], acc[i][3]);
        p[1] = make_float4(acc[i][4], acc[i][5], acc[i][6], acc[i][7]);
    }
}

__device__ __forceinline__ void load_acc(const float* src, float (&acc)[8][8],
                                         int r0, int c0) {
#pragma unroll
    for (int i = 0; i < 8; ++i) {
        const float4* p = (const float4*)(src + (r0 + i) * LDGS + c0);
        float4 v0 = p[0], v1 = p[1];
        acc[i][0] = v0.x; acc[i][1] = v0.y; acc[i][2] = v0.z; acc[i][3] = v0.w;
        acc[i][4] = v1.x; acc[i][5] = v1.y; acc[i][6] = v1.z; acc[i][7] = v1.w;
    }
}

__device__ __forceinline__ void fill_bias(const float* __restrict__ b,
                                          float (&acc)[8][8], int c0) {
#pragma unroll
    for (int j = 0; j < 8; ++j) {
        float bj = b[c0 + j];
#pragma unroll
        for (int i = 0; i < 8; ++i) acc[i][j] = bj;
    }
}

__global__ void __launch_bounds__(256, 1)
traj_kernel(const float* __restrict__ fused,
            const float* __restrict__ intent,
            const float* __restrict__ b_init,
            const float* __restrict__ Wout,
            const float* __restrict__ bout,
            float* __restrict__ out, int B) {
    extern __shared__ float sm[];
    float* g_sh = sm;                          // [32][520] gate scratch
    float* pre0 = sm + ROWS * LDGS;            // [32][520] persistent layer-0 pre
    float* h1T  = pre0 + ROWS * LDGS;          // [128][36] k-major h1
    float* h2T  = h1T + HH * LDT;              // [128][36] k-major h2
    float* xT   = h2T + HH * LDT;              // [129][36] own-row inputs
    float* xiT  = xT + DD * LDT;               // [129][36] init donor-row inputs

    const int tid = threadIdx.x;
    const int cta = blockIdx.x;
    const int tx = tid & 63, ty = tid >> 6;
    const int r0 = ty * 8, c0 = tx * 8;
    const int base = cta * ROWS;
    const int halfB = B >> 1;

    // ---- load inputs (transposed into shared) ----
    for (int idx = tid; idx < ROWS * 128; idx += 256) {
        int r = idx >> 7, k = idx & 127;
        xT[k * LDT + r] = fused[(size_t)(base + r) * 128 + k];
    }
    for (int idx = tid; idx < ROWS * 128; idx += 256) {
        int j = idx >> 7, k = idx & 127;
        int rI = (j < 16) ? (cta * 16 + j) : (halfB + cta * 16 + j - 16);
        xiT[k * LDT + j] = fused[(size_t)rI * 128 + k];
    }
    if (tid < 32) {
        xT[128 * LDT + tid] = intent[base + tid];
    } else if (tid < 64) {
        int j = tid - 32;
        int rI = (j < 16) ? (cta * 16 + j) : (halfB + cta * 16 + j - 16);
        xiT[128 * LDT + j] = intent[rI];
    }
    __syncthreads();

    float acc[8][8];
    float c1r[16], c2r[16];

    // ---- init GEMM: donor rows -> h0/c0 (torch-faithful reshape) ----
    fill_bias(b_init, acc, c0);
    gemm_acc<DD>(acc, g_Wt_init, xiT, r0, c0);
    store_acc(g_sh, acc, r0, c0);
    __syncthreads();

#pragma unroll
    for (int j = 0; j < 16; ++j) {
        int e = tid + 256 * j;
        int b2 = e >> 7, h = e & 127;
        int jr = b2 >> 1;
        int coff = (b2 & 1) * 128 + h;
        c1r[j] = g_sh[jr * LDGS + 256 + coff];
        c2r[j] = g_sh[(16 + jr) * LDGS + 256 + coff];
        h1T[h * LDT + b2] = g_sh[jr * LDGS + coff];
        h2T[h * LDT + b2] = g_sh[(16 + jr) * LDGS + coff];
    }
    __syncthreads();

    // ---- pre0 GEMM: x @ W_ih0^T + (b_ih0 + b_hh0), persistent across steps ----
    fill_bias(g_bpre0, acc, c0);
    gemm_acc<DD>(acc, g_Wt_ih0, xT, r0, c0);
    store_acc(pre0, acc, r0, c0);
    // no barrier needed: each thread re-reads only its own tile of pre0

    for (int t = 0; t < SEQL; ++t) {
        // layer 0 recurrent GEMM: g = pre0 + h1 @ W_hh0^T
        load_acc(pre0, acc, r0, c0);
        gemm_acc<HH>(acc, g_Wt_hh0, h1T, r0, c0);
        store_acc(g_sh, acc, r0, c0);
        __syncthreads();

        // layer 0 pointwise
#pragma unroll
        for (int j = 0; j < 16; ++j) {
            int e = tid + 256 * j;
            int b2 = e >> 7, h = e & 127;
            const float* row = g_sh + b2 * LDGS;
            float vi = row[h], vf = row[128 + h], vg = row[256 + h], vo = row[384 + h];
            float c = sigmoidf_(vf) * c1r[j] + sigmoidf_(vi) * tanhf(vg);
            c1r[j] = c;
            h1T[h * LDT + b2] = sigmoidf_(vo) * tanhf(c);
        }
        __syncthreads();

        // layer 1: g2 = (b_ih1+b_hh1) + h1 @ W_ih1^T + h2 @ W_hh1^T  (fused)
        fill_bias(g_bpre1, acc, c0);
        gemm_acc<HH>(acc, g_Wt_ih1, h1T, r0, c0);
        gemm_acc<HH>(acc, g_Wt_hh1, h2T, r0, c0);
        store_acc(g_sh, acc, r0, c0);
        __syncthreads();

        // layer 1 pointwise
#pragma unroll
        for (int j = 0; j < 16; ++j) {
            int e = tid + 256 * j;
            int b2 = e >> 7, h = e & 127;
            const float* row = g_sh + b2 * LDGS;
            float vi = row[h], vf = row[128 + h], vg = row[256 + h], vo = row[384 + h];
            float c = sigmoidf_(vf) * c2r[j] + sigmoidf_(vi) * tanhf(vg);
            c2r[j] = c;
            h2T[h * LDT + b2] = sigmoidf_(vo) * tanhf(c);
        }
        __syncthreads();

        // output head: out[b, t, o] = h2 . Wout[o] + bout[o]  (2 warps only)
        if (tid < 64) {
            int o = tid >> 5, r = tid & 31;
            const float* wo = Wout + o * HH;
            float s0 = 0.f, s1 = 0.f, s2 = 0.f, s3 = 0.f;
#pragma unroll
            for (int h = 0; h < HH; h += 4) {
                s0 = fmaf(h2T[(h + 0) * LDT + r], wo[h + 0], s0);
                s1 = fmaf(h2T[(h + 1) * LDT + r], wo[h + 1], s1);
                s2 = fmaf(h2T[(h + 2) * LDT + r], wo[h + 2], s2);
                s3 = fmaf(h2T[(h + 3) * LDT + r], wo[h + 3], s3);
            }
            out[(size_t)(base + r) * (SEQL * 2) + t * 2 + o] =
                (s0 + s1) + (s2 + s3) + bout[o];
        }
    }
}

extern "C" void kernel_launch(void* const* d_in, const int* in_sizes, int n_in,
                              void* d_out, int out_size) {
    const float* fused  = (const float*)d_in[0];
    const float* intent = (const float*)d_in[1];
    const float* W_init = (const float*)d_in[2];
    const float* b_init = (const float*)d_in[3];
    const float* W_ih0  = (const float*)d_in[4];
    const float* W_hh0  = (const float*)d_in[5];
    const float* b_ih0  = (const float*)d_in[6];
    const float* b_hh0  = (const float*)d_in[7];
    const float* W_ih1  = (const float*)d_in[8];
    const float* W_hh1  = (const float*)d_in[9];
    const float* b_ih1  = (const float*)d_in[10];
    const float* b_hh1  = (const float*)d_in[11];
    const float* W_out  = (const float*)d_in[12];
    const float* b_out  = (const float*)d_in[13];
    float* out = (float*)d_out;

    int B = in_sizes[0] / 128;   // 131072

    prep_kernel<<<FOURH, 160>>>(W_init, W_ih0, W_hh0, b_ih0, b_hh0,
                                W_ih1, W_hh1, b_ih1, b_hh1);

    const int smem_bytes =
        (2 * ROWS * LDGS + 2 * HH * LDT + 2 * DD * LDT) * (int)sizeof(float);
    cudaFuncSetAttribute(traj_kernel,
                         cudaFuncAttributeMaxDynamicSharedMemorySize, smem_bytes);
    traj_kernel<<<B / ROWS, 256, smem_bytes>>>(fused, intent, b_init,
                                               W_out, b_out, out, B);
}